// round 14
// baseline (speedup 1.0000x reference)
#include <cuda_runtime.h>
#include <cuda_fp16.h>
#include <mma.h>
#include <math.h>
#include <stdint.h>

using namespace nvcuda;

#define NB    4096
#define TT    96
#define NP    12
#define HID   512
#define NLAY  4
#define MLPH  2048
#define NF    11
#define PD    88
#define NROWS (NB*NP)
#define EPS8  1e-8f

// ---------------- scratch (device globals) ----------------
__device__ float  g_feats[(size_t)NB*TT*NF];
__device__ float  g_h[(size_t)NROWS*HID];
__device__ float  g_qkv[(size_t)NROWS*3*HID];
__device__ float  g_c2[(size_t)NB*128];
// activation fp16 hi/lo pairs
__device__ __half g_fh[(size_t)NROWS*PD],   g_fl[(size_t)NROWS*PD];
__device__ __half g_nh[(size_t)NROWS*HID],  g_nl[(size_t)NROWS*HID];
__device__ __half g_oh[(size_t)NROWS*HID],  g_ol[(size_t)NROWS*HID];
__device__ __half g_gh[(size_t)NROWS*MLPH], g_gl[(size_t)NROWS*MLPH];
__device__ __half g_hh[(size_t)NROWS*HID],  g_hl[(size_t)NROWS*HID];
__device__ __half g_c1h[(size_t)NB*512],    g_c1l[(size_t)NB*512];
// weights, split + transposed to [N][K]
__device__ __half g_peTh[512*PD],            g_peTl[512*PD];
__device__ __half g_qkvTh[NLAY*1536*HID],    g_qkvTl[NLAY*1536*HID];
__device__ __half g_outTh[NLAY*HID*HID],     g_outTl[NLAY*HID*HID];
__device__ __half g_m1Th[(size_t)NLAY*MLPH*HID], g_m1Tl[(size_t)NLAY*MLPH*HID];
__device__ __half g_m2Th[(size_t)NLAY*HID*MLPH], g_m2Tl[(size_t)NLAY*HID*MLPH];
__device__ __half g_c1Th[(size_t)512*6144],  g_c1Tl[(size_t)512*6144];
__device__ __half g_c2Th[128*512],           g_c2Tl[128*512];

__device__ __forceinline__ float finz(float v){ return isfinite(v) ? v : 0.f; }
__device__ __forceinline__ void split2(float v, __half& hi, __half& lo){
    hi = __float2half_rn(v);
    lo = __float2half_rn(v - __half2float(hi));
}
__device__ __forceinline__ float gelu_exact(float v){
    return 0.5f * v * (1.0f + erff(v * 0.7071067811865475f));
}

// ---------------- factor engineering ----------------
__global__ void k_factors(const float* __restrict__ x){
    int b = blockIdx.x * blockDim.x + threadIdx.x;
    if (b >= NB) return;
    const float* xr = x + (size_t)b * TT * 5;
    float* fr = g_feats + (size_t)b * TT * NF;
    const float A12 = 2.f/13.f, A26 = 2.f/27.f, A14 = 1.f/14.f;
    float e12=0.f, e26=0.f, ag=0.f, als=0.f, pc=0.f, pv=0.f;
    float cb[20], vb[20];
    float sc=0.f, sc2=0.f, sv=0.f;
    for (int t = 0; t < TT; t++){
        float close = xr[t*5+3];
        float vol   = xr[t*5+4];
        float sva   = (vol > 0.f) ? vol : 1.f;
        if (t == 0){ e12 = close; e26 = close; ag = 0.f; als = 0.f; }
        else {
            e12 = A12*close + (1.f-A12)*e12;
            e26 = A26*close + (1.f-A26)*e26;
            float d = close - pc;
            float gn = d > 0.f ? d : 0.f;
            float ls = d < 0.f ? -d : 0.f;
            ag  = A14*gn + (1.f-A14)*ag;
            als = A14*ls + (1.f-A14)*als;
        }
        float macd = e12 - e26;
        float rs   = ag / (als + 1e-10f);
        float rsi  = (100.f - 100.f/(1.f+rs)) * 0.01f;
        int ri = t % 20;
        if (t < 20){ sc += close; sc2 += close*close; sv += sva; }
        else {
            sc  += close - cb[ri];
            sc2 += close*close - cb[ri]*cb[ri];
            sv  += sva - vb[ri];
        }
        cb[ri] = close; vb[ri] = sva;
        float bb = 0.f, vmr = 1.f;
        if (t >= 19){
            float mean = sc * 0.05f;
            float var  = sc2 * 0.05f - mean*mean; var = var > 0.f ? var : 0.f;
            bb  = 4.f * sqrtf(var) / (mean + EPS8);
            vmr = sva / (sv * 0.05f + EPS8);
        }
        float lr = 0.f, lv = 0.f;
        if (t > 0){
            lr = logf(fmaxf(close, EPS8) / fmaxf(pc, EPS8));
            lv = logf(sva / (pv + EPS8));
        }
        float* o = fr + t*NF;
        o[0]=xr[t*5+0]; o[1]=xr[t*5+1]; o[2]=xr[t*5+2]; o[3]=close; o[4]=vol;
        o[5]=finz(macd); o[6]=finz(rsi); o[7]=finz(bb);
        o[8]=finz(lr);   o[9]=finz(lv);  o[10]=finz(vmr);
        pc = close; pv = sva;
    }
}

// ---------------- per-(b,f) norm over T -> hi/lo halves ----------------
__global__ void k_norm(const float* __restrict__ in_w, const float* __restrict__ in_b){
    int idx = blockIdx.x * blockDim.x + threadIdx.x;
    if (idx >= NB * NF) return;
    int b = idx / NF, f = idx % NF;
    const float* p = g_feats + (size_t)b * TT * NF + f;
    float s = 0.f;
    for (int t = 0; t < TT; t++) s += p[t*NF];
    float m = s * (1.f/TT);
    float v = 0.f;
    for (int t = 0; t < TT; t++){ float d = p[t*NF] - m; v += d*d; }
    float rstd = rsqrtf(v * (1.f/TT) + 1e-5f);
    float w = in_w[f], bi = in_b[f];
    size_t base = (size_t)b * TT * NF + f;
    for (int t = 0; t < TT; t++){
        float val = (p[t*NF] - m) * rstd * w + bi;
        __half hi, lo; split2(val, hi, lo);
        g_fh[base + (size_t)t*NF] = hi;
        g_fl[base + (size_t)t*NF] = lo;
    }
}

// ---------------- LayerNorm -> hi/lo halves ----------------
__global__ void k_ln(const float* __restrict__ h, const float* __restrict__ w,
                     const float* __restrict__ bw, __half* __restrict__ oh,
                     __half* __restrict__ ol){
    int row = blockIdx.x, tid = threadIdx.x;
    const float4 v = reinterpret_cast<const float4*>(h + (size_t)row * HID)[tid];
    __shared__ float sh[4], sh2[4];
    float s = v.x + v.y + v.z + v.w;
    #pragma unroll
    for (int o = 16; o > 0; o >>= 1) s += __shfl_down_sync(0xffffffffu, s, o);
    if ((tid & 31) == 0) sh[tid >> 5] = s;
    __syncthreads();
    float m = (sh[0]+sh[1]+sh[2]+sh[3]) * (1.f/HID);
    float dx=v.x-m, dy=v.y-m, dz=v.z-m, dw=v.w-m;
    float q = dx*dx + dy*dy + dz*dz + dw*dw;
    #pragma unroll
    for (int o = 16; o > 0; o >>= 1) q += __shfl_down_sync(0xffffffffu, q, o);
    if ((tid & 31) == 0) sh2[tid >> 5] = q;
    __syncthreads();
    float rstd = rsqrtf((sh2[0]+sh2[1]+sh2[2]+sh2[3]) * (1.f/HID) + 1e-5f);
    int c = tid * 4;
    float vals[4] = {dx, dy, dz, dw};
    #pragma unroll
    for (int j = 0; j < 4; j++){
        float o = vals[j] * rstd * w[c+j] + bw[c+j];
        __half hi, lo; split2(o, hi, lo);
        oh[(size_t)row*HID + c + j] = hi;
        ol[(size_t)row*HID + c + j] = lo;
    }
}

// ---------------- attention (fp32, small) -> hi/lo halves ----------------
__global__ void k_attn(){
    int bh = blockIdx.x;
    int b = bh >> 3, hh2 = bh & 7;
    __shared__ float qs[12][64], ks[12][64], vs[12][64], ss[12][13];
    int tid = threadIdx.x;
    const float* base = g_qkv + (size_t)b * 12 * 1536 + hh2 * 64;
    #pragma unroll
    for (int p = 0; p < 12; p++){
        qs[p][tid] = base[p*1536 + tid];
        ks[p][tid] = base[p*1536 + 512 + tid];
        vs[p][tid] = base[p*1536 + 1024 + tid];
    }
    __syncthreads();
    for (int idx = tid; idx < 144; idx += 64){
        int i = idx / 12, j = idx % 12;
        float acc = 0.f;
        #pragma unroll
        for (int d = 0; d < 64; d++) acc += qs[i][d] * ks[j][d];
        ss[i][j] = acc * 0.125f;
    }
    __syncthreads();
    if (tid < 12){
        float m = -1e30f;
        #pragma unroll
        for (int j = 0; j < 12; j++) m = fmaxf(m, ss[tid][j]);
        float su = 0.f;
        #pragma unroll
        for (int j = 0; j < 12; j++){ float e = expf(ss[tid][j]-m); ss[tid][j]=e; su+=e; }
        float inv = 1.f / su;
        #pragma unroll
        for (int j = 0; j < 12; j++) ss[tid][j] *= inv;
    }
    __syncthreads();
    for (int idx = tid; idx < 768; idx += 64){
        int i = idx >> 6, d = idx & 63;
        float acc = 0.f;
        #pragma unroll
        for (int j = 0; j < 12; j++) acc += ss[i][j] * vs[j][d];
        size_t o = ((size_t)b*12 + i) * HID + hh2*64 + d;
        __half hi, lo; split2(acc, hi, lo);
        g_oh[o] = hi; g_ol[o] = lo;
    }
}

// ---------------- weight split + transpose: W[K][N] -> WT hi/lo [N][K] ----------------
__global__ void k_wsplit(const float* __restrict__ W, __half* __restrict__ Wh,
                         __half* __restrict__ Wl, int K, int N){
    __shared__ float t[32][33];
    int kb = blockIdx.y*32, nb = blockIdx.x*32;
    int tx = threadIdx.x, ty = threadIdx.y;
    for (int i = ty; i < 32; i += 8){
        int k = kb + i, n = nb + tx;
        t[i][tx] = (k < K && n < N) ? W[(size_t)k*N + n] : 0.f;
    }
    __syncthreads();
    for (int i = ty; i < 32; i += 8){
        int n = nb + i, k = kb + tx;
        if (n < N && k < K){
            __half hi, lo; split2(t[tx][i], hi, lo);
            Wh[(size_t)n*K + k] = hi;
            Wl[(size_t)n*K + k] = lo;
        }
    }
}

// ---------------- split-fp16 WMMA GEMM, CTA 128x256, warp 64x64, 3-stage cp.async ----------------
// C[M,N] = (Ah+Al)[M,K] @ (Bh+Bl)^T  (B stored [N][K])  + bias [+resid] [gelu]
#define BM  128
#define BN  256
#define BK  32
#define AST 40
// A region: [3 stages][2 hl][128][AST]; B region: [3][2][256][AST]
#define A_HALVES (3*2*128*AST)
#define B_HALVES (3*2*256*AST)
#define GSM_BYTES ((A_HALVES + B_HALVES) * 2)   // 184320

__device__ __forceinline__ void cpa16(__half* dst, const void* src, int sz){
    asm volatile("cp.async.cg.shared.global [%0], [%1], 16, %2;"
                 :: "r"((uint32_t)__cvta_generic_to_shared(dst)), "l"(src), "r"(sz)
                 : "memory");
}

template<bool GELU, bool RESID>
__global__ __launch_bounds__(256, 1)
void k_gemm(const __half* __restrict__ Ah, const __half* __restrict__ Al,
            const __half* __restrict__ Bh, const __half* __restrict__ Bl,
            const float* __restrict__ bias, const float* __restrict__ resid,
            float* __restrict__ outF, __half* __restrict__ outH,
            __half* __restrict__ outL, int M, int N, int K)
{
    extern __shared__ __align__(16) unsigned char dyn[];
    __half* smA = reinterpret_cast<__half*>(dyn);
    __half* smB = smA + A_HALVES;
    int tid = threadIdx.x;
    int warp = tid >> 5, lane = tid & 31;
    int wm = warp >> 2, wn = warp & 3;       // 2 x 4 warps, each 64x64
    int m0 = blockIdx.y * BM, n0 = blockIdx.x * BN;
    int KT = (K + BK - 1) / BK;

    wmma::fragment<wmma::accumulator,16,16,16,float> acc[4][4];
    #pragma unroll
    for (int mi = 0; mi < 4; mi++)
        #pragma unroll
        for (int ni = 0; ni < 4; ni++) wmma::fill_fragment(acc[mi][ni], 0.f);

    // stage issue: A 1024 vectors + B 2048 vectors (16B each) -> 12 per thread
    auto issue = [&](int kt, int s){
        int k0 = kt * BK;
        #pragma unroll
        for (int j = 0; j < 4; j++){
            int v = j*256 + tid;
            int hl = v >> 9, r = (v >> 2) & 127, c4 = v & 3;
            const __half* src = (hl ? Al : Ah) + (size_t)(m0+r)*K + k0 + c4*8;
            __half* d = smA + ((size_t)((s*2+hl)*128 + r))*AST + c4*8;
            cpa16(d, src, (k0 + c4*8 < K) ? 16 : 0);
        }
        #pragma unroll
        for (int j = 0; j < 8; j++){
            int v = j*256 + tid;
            int hl = v >> 10, r = (v >> 2) & 255, c4 = v & 3;
            const __half* src = (hl ? Bl : Bh) + (size_t)(n0+r)*K + k0 + c4*8;
            __half* d = smB + ((size_t)((s*2+hl)*256 + r))*AST + c4*8;
            cpa16(d, src, (n0 + r < N && k0 + c4*8 < K) ? 16 : 0);
        }
        asm volatile("cp.async.commit_group;" ::: "memory");
    };

    issue(0, 0);
    if (KT > 1) issue(1, 1);

    for (int kt = 0; kt < KT; kt++){
        int s = kt % 3;
        if (kt + 1 < KT) asm volatile("cp.async.wait_group 1;" ::: "memory");
        else             asm volatile("cp.async.wait_group 0;" ::: "memory");
        __syncthreads();   // stage s ready; also fences compute(kt-1) before stage reuse below
        if (kt + 2 < KT) issue(kt+2, (kt+2) % 3);
        // compute on stage s
        #pragma unroll
        for (int ks = 0; ks < 2; ks++){
            wmma::fragment<wmma::matrix_b,16,16,16,__half,wmma::col_major> fbh[4], fbl[4];
            #pragma unroll
            for (int ni = 0; ni < 4; ni++){
                wmma::load_matrix_sync(fbh[ni], smB + ((size_t)((s*2+0)*256 + wn*64+ni*16))*AST + ks*16, AST);
                wmma::load_matrix_sync(fbl[ni], smB + ((size_t)((s*2+1)*256 + wn*64+ni*16))*AST + ks*16, AST);
            }
            #pragma unroll
            for (int mi = 0; mi < 4; mi++){
                wmma::fragment<wmma::matrix_a,16,16,16,__half,wmma::row_major> fah, fal;
                wmma::load_matrix_sync(fah, smA + ((size_t)((s*2+0)*128 + wm*64+mi*16))*AST + ks*16, AST);
                wmma::load_matrix_sync(fal, smA + ((size_t)((s*2+1)*128 + wm*64+mi*16))*AST + ks*16, AST);
                #pragma unroll
                for (int ni = 0; ni < 4; ni++){
                    wmma::mma_sync(acc[mi][ni], fah, fbh[ni], acc[mi][ni]);
                    wmma::mma_sync(acc[mi][ni], fah, fbl[ni], acc[mi][ni]);
                    wmma::mma_sync(acc[mi][ni], fal, fbh[ni], acc[mi][ni]);
                }
            }
        }
    }
    __syncthreads();   // all compute done before epilogue aliases smem

    // epilogue: per-warp 16x16 staging through smem
    float* epi = reinterpret_cast<float*>(dyn) + warp * 256;
    #pragma unroll
    for (int mi = 0; mi < 4; mi++){
        #pragma unroll
        for (int ni = 0; ni < 4; ni++){
            wmma::store_matrix_sync(epi, acc[mi][ni], 16, wmma::mem_row_major);
            __syncwarp();
            #pragma unroll
            for (int j = 0; j < 8; j++){
                int e = j*32 + lane;
                int r = e >> 4, c = e & 15;
                int gr = m0 + wm*64 + mi*16 + r;
                int gc = n0 + wn*64 + ni*16 + c;
                if (gc < N){
                    float v = epi[r*16 + c] + bias[gc];
                    if (RESID) v += resid[(size_t)gr*N + gc];
                    if (GELU)  v = gelu_exact(v);
                    if (outF) outF[(size_t)gr*N + gc] = v;
                    if (outH){
                        __half hi, lo; split2(v, hi, lo);
                        outH[(size_t)gr*N + gc] = hi;
                        outL[(size_t)gr*N + gc] = lo;
                    }
                }
            }
            __syncwarp();
        }
    }
}

// ---------------- final tiny GEMM: (4096,128)x(128,3) ----------------
__global__ void k_cls3(const float* __restrict__ w3, const float* __restrict__ b3,
                       float* __restrict__ out){
    int i = blockIdx.x * blockDim.x + threadIdx.x;
    if (i >= NB * 3) return;
    int b = i / 3, c = i % 3;
    const float* f = g_c2 + (size_t)b * 128;
    float acc = b3[c];
    #pragma unroll 4
    for (int k = 0; k < 128; k++) acc += f[k] * w3[k*3 + c];
    out[i] = acc;
}

// ---------------- launch ----------------
extern "C" void kernel_launch(void* const* d_in, const int* in_sizes, int n_in,
                              void* d_out, int out_size) {
    const float* x      = (const float*)d_in[0];
    const float* in_w   = (const float*)d_in[1];
    const float* in_b   = (const float*)d_in[2];
    const float* pe_w   = (const float*)d_in[3];
    const float* pe_b   = (const float*)d_in[4];
    const float* ln1_w  = (const float*)d_in[5];
    const float* ln1_b  = (const float*)d_in[6];
    const float* qkv_w  = (const float*)d_in[7];
    const float* qkv_b  = (const float*)d_in[8];
    const float* out_w  = (const float*)d_in[9];
    const float* out_b  = (const float*)d_in[10];
    const float* ln2_w  = (const float*)d_in[11];
    const float* ln2_b  = (const float*)d_in[12];
    const float* mlp_w1 = (const float*)d_in[13];
    const float* mlp_b1 = (const float*)d_in[14];
    const float* mlp_w2 = (const float*)d_in[15];
    const float* mlp_b2 = (const float*)d_in[16];
    const float* cls_w1 = (const float*)d_in[17];
    const float* cls_b1 = (const float*)d_in[18];
    const float* cls_w2 = (const float*)d_in[19];
    const float* cls_b2 = (const float*)d_in[20];
    const float* cls_w3 = (const float*)d_in[21];
    const float* cls_b3 = (const float*)d_in[22];
    float* out = (float*)d_out;

    cudaFuncSetAttribute(k_gemm<false,false>, cudaFuncAttributeMaxDynamicSharedMemorySize, GSM_BYTES);
    cudaFuncSetAttribute(k_gemm<false,true>,  cudaFuncAttributeMaxDynamicSharedMemorySize, GSM_BYTES);
    cudaFuncSetAttribute(k_gemm<true,false>,  cudaFuncAttributeMaxDynamicSharedMemorySize, GSM_BYTES);

    float *p_h, *p_qkv, *p_c2f;
    __half *p_fh,*p_fl,*p_nh,*p_nl,*p_oh,*p_ol,*p_gh,*p_gl,*p_hh,*p_hl,*p_c1h,*p_c1l;
    __half *p_peTh,*p_peTl,*p_qkvTh,*p_qkvTl,*p_outTh,*p_outTl;
    __half *p_m1Th,*p_m1Tl,*p_m2Th,*p_m2Tl,*p_c1Th,*p_c1Tl,*p_c2Th,*p_c2Tl;
    cudaGetSymbolAddress((void**)&p_h,    g_h);
    cudaGetSymbolAddress((void**)&p_qkv,  g_qkv);
    cudaGetSymbolAddress((void**)&p_c2f,  g_c2);
    cudaGetSymbolAddress((void**)&p_fh,   g_fh);   cudaGetSymbolAddress((void**)&p_fl,   g_fl);
    cudaGetSymbolAddress((void**)&p_nh,   g_nh);   cudaGetSymbolAddress((void**)&p_nl,   g_nl);
    cudaGetSymbolAddress((void**)&p_oh,   g_oh);   cudaGetSymbolAddress((void**)&p_ol,   g_ol);
    cudaGetSymbolAddress((void**)&p_gh,   g_gh);   cudaGetSymbolAddress((void**)&p_gl,   g_gl);
    cudaGetSymbolAddress((void**)&p_hh,   g_hh);   cudaGetSymbolAddress((void**)&p_hl,   g_hl);
    cudaGetSymbolAddress((void**)&p_c1h,  g_c1h);  cudaGetSymbolAddress((void**)&p_c1l,  g_c1l);
    cudaGetSymbolAddress((void**)&p_peTh, g_peTh); cudaGetSymbolAddress((void**)&p_peTl, g_peTl);
    cudaGetSymbolAddress((void**)&p_qkvTh,g_qkvTh);cudaGetSymbolAddress((void**)&p_qkvTl,g_qkvTl);
    cudaGetSymbolAddress((void**)&p_outTh,g_outTh);cudaGetSymbolAddress((void**)&p_outTl,g_outTl);
    cudaGetSymbolAddress((void**)&p_m1Th, g_m1Th); cudaGetSymbolAddress((void**)&p_m1Tl, g_m1Tl);
    cudaGetSymbolAddress((void**)&p_m2Th, g_m2Th); cudaGetSymbolAddress((void**)&p_m2Tl, g_m2Tl);
    cudaGetSymbolAddress((void**)&p_c1Th, g_c1Th); cudaGetSymbolAddress((void**)&p_c1Tl, g_c1Tl);
    cudaGetSymbolAddress((void**)&p_c2Th, g_c2Th); cudaGetSymbolAddress((void**)&p_c2Tl, g_c2Tl);

    dim3 wb(32, 8);
    k_wsplit<<<dim3(16, 3),  wb>>>(pe_w,  p_peTh, p_peTl, PD, 512);
    for (int i = 0; i < NLAY; i++){
        k_wsplit<<<dim3(48, 16), wb>>>(qkv_w + (size_t)i*HID*1536, p_qkvTh + (size_t)i*1536*HID, p_qkvTl + (size_t)i*1536*HID, HID, 1536);
        k_wsplit<<<dim3(16, 16), wb>>>(out_w + (size_t)i*HID*HID,  p_outTh + (size_t)i*HID*HID,  p_outTl + (size_t)i*HID*HID,  HID, HID);
        k_wsplit<<<dim3(64, 16), wb>>>(mlp_w1 + (size_t)i*HID*MLPH, p_m1Th + (size_t)i*MLPH*HID, p_m1Tl + (size_t)i*MLPH*HID, HID, MLPH);
        k_wsplit<<<dim3(16, 64), wb>>>(mlp_w2 + (size_t)i*MLPH*HID, p_m2Th + (size_t)i*HID*MLPH, p_m2Tl + (size_t)i*HID*MLPH, MLPH, HID);
    }
    k_wsplit<<<dim3(16, 192), wb>>>(cls_w1, p_c1Th, p_c1Tl, 6144, 512);
    k_wsplit<<<dim3(4, 16),   wb>>>(cls_w2, p_c2Th, p_c2Tl, 512, 128);

    k_factors<<<(NB+255)/256, 256>>>(x);
    k_norm<<<(NB*NF+255)/256, 256>>>(in_w, in_b);

    // patch embed -> h (fp32)
    k_gemm<false,false><<<dim3(2, NROWS/BM), 256, GSM_BYTES>>>(
        p_fh, p_fl, p_peTh, p_peTl, pe_b, nullptr, p_h, nullptr, nullptr, NROWS, 512, PD);

    for (int i = 0; i < NLAY; i++){
        k_ln<<<NROWS, 128>>>(p_h, ln1_w + i*HID, ln1_b + i*HID, p_nh, p_nl);
        k_gemm<false,false><<<dim3(6, NROWS/BM), 256, GSM_BYTES>>>(
            p_nh, p_nl, p_qkvTh + (size_t)i*1536*HID, p_qkvTl + (size_t)i*1536*HID,
            qkv_b + i*1536, nullptr, p_qkv, nullptr, nullptr, NROWS, 1536, HID);
        k_attn<<<NB*8, 64>>>();
        k_gemm<false,true><<<dim3(2, NROWS/BM), 256, GSM_BYTES>>>(
            p_oh, p_ol, p_outTh + (size_t)i*HID*HID, p_outTl + (size_t)i*HID*HID,
            out_b + i*HID, p_h, p_h, nullptr, nullptr, NROWS, HID, HID);
        k_ln<<<NROWS, 128>>>(p_h, ln2_w + i*HID, ln2_b + i*HID, p_nh, p_nl);
        k_gemm<true,false><<<dim3(8, NROWS/BM), 256, GSM_BYTES>>>(
            p_nh, p_nl, p_m1Th + (size_t)i*MLPH*HID, p_m1Tl + (size_t)i*MLPH*HID,
            mlp_b1 + i*MLPH, nullptr, nullptr, p_gh, p_gl, NROWS, MLPH, HID);
        // last layer also emits the hi/lo pair for the cls head (fuses k_split away)
        k_gemm<false,true><<<dim3(2, NROWS/BM), 256, GSM_BYTES>>>(
            p_gh, p_gl, p_m2Th + (size_t)i*HID*MLPH, p_m2Tl + (size_t)i*HID*MLPH,
            mlp_b2 + i*HID, p_h, p_h,
            (i == NLAY-1) ? p_hh : nullptr, (i == NLAY-1) ? p_hl : nullptr,
            NROWS, HID, MLPH);
    }

    // cls head: h viewed as (4096, 6144)
    k_gemm<true,false><<<dim3(2, NB/BM), 256, GSM_BYTES>>>(
        p_hh, p_hl, p_c1Th, p_c1Tl, cls_b1, nullptr, nullptr, p_c1h, p_c1l, NB, 512, 6144);
    k_gemm<true,false><<<dim3(1, NB/BM), 256, GSM_BYTES>>>(
        p_c1h, p_c1l, p_c2Th, p_c2Tl, cls_b2, nullptr, p_c2f, nullptr, nullptr, NB, 128, 512);
    k_cls3<<<(NB*3+255)/256, 256>>>(cls_w3, cls_b3, out);
}

// round 16
// speedup vs baseline: 1.3815x; 1.3815x over previous
#include <cuda_runtime.h>
#include <cuda_fp16.h>
#include <mma.h>
#include <math.h>
#include <stdint.h>

using namespace nvcuda;

#define NB    4096
#define TT    96
#define NP    12
#define HID   512
#define NLAY  4
#define MLPH  2048
#define NF    11
#define PD    88
#define NROWS (NB*NP)
#define EPS8  1e-8f

// ---------------- scratch (device globals) ----------------
__device__ float  g_feats[(size_t)NB*TT*NF];
__device__ float  g_h[(size_t)NROWS*HID];
__device__ float  g_qkv[(size_t)NROWS*3*HID];
__device__ float  g_c2[(size_t)NB*128];
// activation fp16 hi/lo pairs
__device__ __half g_fh[(size_t)NROWS*PD],   g_fl[(size_t)NROWS*PD];
__device__ __half g_nh[(size_t)NROWS*HID],  g_nl[(size_t)NROWS*HID];
__device__ __half g_oh[(size_t)NROWS*HID],  g_ol[(size_t)NROWS*HID];
__device__ __half g_gh[(size_t)NROWS*MLPH], g_gl[(size_t)NROWS*MLPH];
__device__ __half g_hh[(size_t)NROWS*HID],  g_hl[(size_t)NROWS*HID];
__device__ __half g_c1h[(size_t)NB*512],    g_c1l[(size_t)NB*512];
// weights, split + transposed to [N][K]
__device__ __half g_peTh[512*PD],            g_peTl[512*PD];
__device__ __half g_qkvTh[NLAY*1536*HID],    g_qkvTl[NLAY*1536*HID];
__device__ __half g_outTh[NLAY*HID*HID],     g_outTl[NLAY*HID*HID];
__device__ __half g_m1Th[(size_t)NLAY*MLPH*HID], g_m1Tl[(size_t)NLAY*MLPH*HID];
__device__ __half g_m2Th[(size_t)NLAY*HID*MLPH], g_m2Tl[(size_t)NLAY*HID*MLPH];
__device__ __half g_c1Th[(size_t)512*6144],  g_c1Tl[(size_t)512*6144];
__device__ __half g_c2Th[128*512],           g_c2Tl[128*512];

__device__ __forceinline__ float finz(float v){ return isfinite(v) ? v : 0.f; }
__device__ __forceinline__ void split2(float v, __half& hi, __half& lo){
    hi = __float2half_rn(v);
    lo = __float2half_rn(v - __half2float(hi));
}
__device__ __forceinline__ float gelu_exact(float v){
    return 0.5f * v * (1.0f + erff(v * 0.7071067811865475f));
}

// ---------------- factor engineering ----------------
__global__ void k_factors(const float* __restrict__ x){
    int b = blockIdx.x * blockDim.x + threadIdx.x;
    if (b >= NB) return;
    const float* xr = x + (size_t)b * TT * 5;
    float* fr = g_feats + (size_t)b * TT * NF;
    const float A12 = 2.f/13.f, A26 = 2.f/27.f, A14 = 1.f/14.f;
    float e12=0.f, e26=0.f, ag=0.f, als=0.f, pc=0.f, pv=0.f;
    float cb[20], vb[20];
    float sc=0.f, sc2=0.f, sv=0.f;
    for (int t = 0; t < TT; t++){
        float close = xr[t*5+3];
        float vol   = xr[t*5+4];
        float sva   = (vol > 0.f) ? vol : 1.f;
        if (t == 0){ e12 = close; e26 = close; ag = 0.f; als = 0.f; }
        else {
            e12 = A12*close + (1.f-A12)*e12;
            e26 = A26*close + (1.f-A26)*e26;
            float d = close - pc;
            float gn = d > 0.f ? d : 0.f;
            float ls = d < 0.f ? -d : 0.f;
            ag  = A14*gn + (1.f-A14)*ag;
            als = A14*ls + (1.f-A14)*als;
        }
        float macd = e12 - e26;
        float rs   = ag / (als + 1e-10f);
        float rsi  = (100.f - 100.f/(1.f+rs)) * 0.01f;
        int ri = t % 20;
        if (t < 20){ sc += close; sc2 += close*close; sv += sva; }
        else {
            sc  += close - cb[ri];
            sc2 += close*close - cb[ri]*cb[ri];
            sv  += sva - vb[ri];
        }
        cb[ri] = close; vb[ri] = sva;
        float bb = 0.f, vmr = 1.f;
        if (t >= 19){
            float mean = sc * 0.05f;
            float var  = sc2 * 0.05f - mean*mean; var = var > 0.f ? var : 0.f;
            bb  = 4.f * sqrtf(var) / (mean + EPS8);
            vmr = sva / (sv * 0.05f + EPS8);
        }
        float lr = 0.f, lv = 0.f;
        if (t > 0){
            lr = logf(fmaxf(close, EPS8) / fmaxf(pc, EPS8));
            lv = logf(sva / (pv + EPS8));
        }
        float* o = fr + t*NF;
        o[0]=xr[t*5+0]; o[1]=xr[t*5+1]; o[2]=xr[t*5+2]; o[3]=close; o[4]=vol;
        o[5]=finz(macd); o[6]=finz(rsi); o[7]=finz(bb);
        o[8]=finz(lr);   o[9]=finz(lv);  o[10]=finz(vmr);
        pc = close; pv = sva;
    }
}

// ---------------- per-(b,f) norm over T -> hi/lo halves ----------------
__global__ void k_norm(const float* __restrict__ in_w, const float* __restrict__ in_b){
    int idx = blockIdx.x * blockDim.x + threadIdx.x;
    if (idx >= NB * NF) return;
    int b = idx / NF, f = idx % NF;
    const float* p = g_feats + (size_t)b * TT * NF + f;
    float s = 0.f;
    for (int t = 0; t < TT; t++) s += p[t*NF];
    float m = s * (1.f/TT);
    float v = 0.f;
    for (int t = 0; t < TT; t++){ float d = p[t*NF] - m; v += d*d; }
    float rstd = rsqrtf(v * (1.f/TT) + 1e-5f);
    float w = in_w[f], bi = in_b[f];
    size_t base = (size_t)b * TT * NF + f;
    for (int t = 0; t < TT; t++){
        float val = (p[t*NF] - m) * rstd * w + bi;
        __half hi, lo; split2(val, hi, lo);
        g_fh[base + (size_t)t*NF] = hi;
        g_fl[base + (size_t)t*NF] = lo;
    }
}

// ---------------- LayerNorm -> hi/lo halves ----------------
__global__ void k_ln(const float* __restrict__ h, const float* __restrict__ w,
                     const float* __restrict__ bw, __half* __restrict__ oh,
                     __half* __restrict__ ol){
    int row = blockIdx.x, tid = threadIdx.x;
    const float4 v = reinterpret_cast<const float4*>(h + (size_t)row * HID)[tid];
    __shared__ float sh[4], sh2[4];
    float s = v.x + v.y + v.z + v.w;
    #pragma unroll
    for (int o = 16; o > 0; o >>= 1) s += __shfl_down_sync(0xffffffffu, s, o);
    if ((tid & 31) == 0) sh[tid >> 5] = s;
    __syncthreads();
    float m = (sh[0]+sh[1]+sh[2]+sh[3]) * (1.f/HID);
    float dx=v.x-m, dy=v.y-m, dz=v.z-m, dw=v.w-m;
    float q = dx*dx + dy*dy + dz*dz + dw*dw;
    #pragma unroll
    for (int o = 16; o > 0; o >>= 1) q += __shfl_down_sync(0xffffffffu, q, o);
    if ((tid & 31) == 0) sh2[tid >> 5] = q;
    __syncthreads();
    float rstd = rsqrtf((sh2[0]+sh2[1]+sh2[2]+sh2[3]) * (1.f/HID) + 1e-5f);
    int c = tid * 4;
    float vals[4] = {dx, dy, dz, dw};
    #pragma unroll
    for (int j = 0; j < 4; j++){
        float o = vals[j] * rstd * w[c+j] + bw[c+j];
        __half hi, lo; split2(o, hi, lo);
        oh[(size_t)row*HID + c + j] = hi;
        ol[(size_t)row*HID + c + j] = lo;
    }
}

// ---------------- attention (fp32, small) -> hi/lo halves ----------------
__global__ void k_attn(){
    int bh = blockIdx.x;
    int b = bh >> 3, hh2 = bh & 7;
    __shared__ float qs[12][64], ks[12][64], vs[12][64], ss[12][13];
    int tid = threadIdx.x;
    const float* base = g_qkv + (size_t)b * 12 * 1536 + hh2 * 64;
    #pragma unroll
    for (int p = 0; p < 12; p++){
        qs[p][tid] = base[p*1536 + tid];
        ks[p][tid] = base[p*1536 + 512 + tid];
        vs[p][tid] = base[p*1536 + 1024 + tid];
    }
    __syncthreads();
    for (int idx = tid; idx < 144; idx += 64){
        int i = idx / 12, j = idx % 12;
        float acc = 0.f;
        #pragma unroll
        for (int d = 0; d < 64; d++) acc += qs[i][d] * ks[j][d];
        ss[i][j] = acc * 0.125f;
    }
    __syncthreads();
    if (tid < 12){
        float m = -1e30f;
        #pragma unroll
        for (int j = 0; j < 12; j++) m = fmaxf(m, ss[tid][j]);
        float su = 0.f;
        #pragma unroll
        for (int j = 0; j < 12; j++){ float e = expf(ss[tid][j]-m); ss[tid][j]=e; su+=e; }
        float inv = 1.f / su;
        #pragma unroll
        for (int j = 0; j < 12; j++) ss[tid][j] *= inv;
    }
    __syncthreads();
    for (int idx = tid; idx < 768; idx += 64){
        int i = idx >> 6, d = idx & 63;
        float acc = 0.f;
        #pragma unroll
        for (int j = 0; j < 12; j++) acc += ss[i][j] * vs[j][d];
        size_t o = ((size_t)b*12 + i) * HID + hh2*64 + d;
        __half hi, lo; split2(acc, hi, lo);
        g_oh[o] = hi; g_ol[o] = lo;
    }
}

// ---------------- weight split + transpose: W[K][N] -> WT hi/lo [N][K] ----------------
__global__ void k_wsplit(const float* __restrict__ W, __half* __restrict__ Wh,
                         __half* __restrict__ Wl, int K, int N){
    __shared__ float t[32][33];
    int kb = blockIdx.y*32, nb = blockIdx.x*32;
    int tx = threadIdx.x, ty = threadIdx.y;
    for (int i = ty; i < 32; i += 8){
        int k = kb + i, n = nb + tx;
        t[i][tx] = (k < K && n < N) ? W[(size_t)k*N + n] : 0.f;
    }
    __syncthreads();
    for (int i = ty; i < 32; i += 8){
        int n = nb + i, k = kb + tx;
        if (n < N && k < K){
            __half hi, lo; split2(t[tx][i], hi, lo);
            Wh[(size_t)n*K + k] = hi;
            Wl[(size_t)n*K + k] = lo;
        }
    }
}

// ---------------- split-fp16 WMMA GEMM, CTA 128x128, warp 64x32, 2-stage, 1 barrier/iter ----------------
// C[M,N] = (Ah+Al)[M,K] @ (Bh+Bl)^T  (B stored [N][K])  + bias [+resid] [gelu]
#define BM  128
#define BN  128
#define BK  32
#define AST 40                         // halves per smem row (80B stride)
#define STG_HALVES (2*2*128*AST)       // per-operand: [2 stages][2 hl][128][40]
#define EPI_STRIDE 132
#define GSM_BYTES (2*STG_HALVES*2)     // 81920 bytes (>= 128*132*4 = 67584 epi)

__device__ __forceinline__ void cpa16(__half* dst, const void* src, int sz){
    asm volatile("cp.async.cg.shared.global [%0], [%1], 16, %2;"
                 :: "r"((uint32_t)__cvta_generic_to_shared(dst)), "l"(src), "r"(sz)
                 : "memory");
}

template<bool GELU, bool RESID>
__global__ __launch_bounds__(256)
void k_gemm(const __half* __restrict__ Ah, const __half* __restrict__ Al,
            const __half* __restrict__ Bh, const __half* __restrict__ Bl,
            const float* __restrict__ bias, const float* __restrict__ resid,
            float* __restrict__ outF, __half* __restrict__ outH,
            __half* __restrict__ outL, int M, int N, int K)
{
    extern __shared__ __align__(16) unsigned char dyn[];
    __half* smA = reinterpret_cast<__half*>(dyn);
    __half* smB = smA + STG_HALVES;
    int tid = threadIdx.x;
    int warp = tid >> 5, lane = tid & 31;
    int wm = warp >> 2, wn = warp & 3;       // 2 x 4 warps, each 64x32
    int m0 = blockIdx.y * BM, n0 = blockIdx.x * BN;
    int KT = (K + BK - 1) / BK;

    wmma::fragment<wmma::accumulator,16,16,16,float> acc[4][2];
    #pragma unroll
    for (int mi = 0; mi < 4; mi++)
        #pragma unroll
        for (int ni = 0; ni < 2; ni++) wmma::fill_fragment(acc[mi][ni], 0.f);

    // stage issue: 1024 A-vectors + 1024 B-vectors (16B each), 8 per thread
    auto issue = [&](int kt, int s){
        int k0 = kt * BK;
        #pragma unroll
        for (int j = 0; j < 4; j++){
            int v = j*256 + tid;
            int hl = v >> 9, r = (v >> 2) & 127, c4 = v & 3;
            const __half* src = (hl ? Al : Ah) + (size_t)(m0+r)*K + k0 + c4*8;
            __half* d = smA + ((size_t)((s*2+hl)*128 + r))*AST + c4*8;
            cpa16(d, src, (k0 + c4*8 < K) ? 16 : 0);
        }
        #pragma unroll
        for (int j = 0; j < 4; j++){
            int v = j*256 + tid;
            int hl = v >> 9, r = (v >> 2) & 127, c4 = v & 3;
            const __half* src = (hl ? Bl : Bh) + (size_t)(n0+r)*K + k0 + c4*8;
            __half* d = smB + ((size_t)((s*2+hl)*128 + r))*AST + c4*8;
            cpa16(d, src, (k0 + c4*8 < K) ? 16 : 0);
        }
        asm volatile("cp.async.commit_group;" ::: "memory");
    };

    issue(0, 0);
    for (int kt = 0; kt < KT; kt++){
        int s = kt & 1;
        asm volatile("cp.async.wait_group 0;" ::: "memory");
        __syncthreads();            // stage s ready; fences compute(kt-1) before s^1 reuse
        if (kt + 1 < KT) issue(kt+1, s^1);   // overlaps with compute below
        #pragma unroll
        for (int ks = 0; ks < 2; ks++){
            wmma::fragment<wmma::matrix_b,16,16,16,__half,wmma::col_major> fbh[2], fbl[2];
            #pragma unroll
            for (int ni = 0; ni < 2; ni++){
                wmma::load_matrix_sync(fbh[ni], smB + ((size_t)((s*2+0)*128 + wn*32+ni*16))*AST + ks*16, AST);
                wmma::load_matrix_sync(fbl[ni], smB + ((size_t)((s*2+1)*128 + wn*32+ni*16))*AST + ks*16, AST);
            }
            #pragma unroll
            for (int mi = 0; mi < 4; mi++){
                wmma::fragment<wmma::matrix_a,16,16,16,__half,wmma::row_major> fah, fal;
                wmma::load_matrix_sync(fah, smA + ((size_t)((s*2+0)*128 + wm*64+mi*16))*AST + ks*16, AST);
                wmma::load_matrix_sync(fal, smA + ((size_t)((s*2+1)*128 + wm*64+mi*16))*AST + ks*16, AST);
                #pragma unroll
                for (int ni = 0; ni < 2; ni++){
                    wmma::mma_sync(acc[mi][ni], fah, fbh[ni], acc[mi][ni]);
                    wmma::mma_sync(acc[mi][ni], fah, fbl[ni], acc[mi][ni]);
                    wmma::mma_sync(acc[mi][ni], fal, fbh[ni], acc[mi][ni]);
                }
            }
        }
    }
    __syncthreads();   // compute done before epilogue aliases smem

    // epilogue: stage full 128x128 fp32 tile, then coalesced vector writes
    float* stg = reinterpret_cast<float*>(dyn);
    #pragma unroll
    for (int mi = 0; mi < 4; mi++)
        #pragma unroll
        for (int ni = 0; ni < 2; ni++)
            wmma::store_matrix_sync(stg + (size_t)(wm*64+mi*16)*EPI_STRIDE + wn*32+ni*16,
                                    acc[mi][ni], EPI_STRIDE, wmma::mem_row_major);
    __syncthreads();
    for (int v = tid; v < 128*32; v += 256){
        int r = v >> 5, c4 = (v & 31) * 4;
        int gr = m0 + r, gc = n0 + c4;
        float4 val = *reinterpret_cast<const float4*>(stg + (size_t)r*EPI_STRIDE + c4);
        const float4 bi = *reinterpret_cast<const float4*>(bias + gc);
        val.x += bi.x; val.y += bi.y; val.z += bi.z; val.w += bi.w;
        if (RESID){
            const float4 rs = *reinterpret_cast<const float4*>(resid + (size_t)gr*N + gc);
            val.x += rs.x; val.y += rs.y; val.z += rs.z; val.w += rs.w;
        }
        if (GELU){
            val.x = gelu_exact(val.x); val.y = gelu_exact(val.y);
            val.z = gelu_exact(val.z); val.w = gelu_exact(val.w);
        }
        if (outF) *reinterpret_cast<float4*>(outF + (size_t)gr*N + gc) = val;
        if (outH){
            __half h0,l0,h1,l1,h2,l2,h3,l3;
            split2(val.x,h0,l0); split2(val.y,h1,l1);
            split2(val.z,h2,l2); split2(val.w,h3,l3);
            __half2 hh0 = __halves2half2(h0,h1), hh1 = __halves2half2(h2,h3);
            __half2 ll0 = __halves2half2(l0,l1), ll1 = __halves2half2(l2,l3);
            *reinterpret_cast<__half2*>(outH + (size_t)gr*N + gc)     = hh0;
            *reinterpret_cast<__half2*>(outH + (size_t)gr*N + gc + 2) = hh1;
            *reinterpret_cast<__half2*>(outL + (size_t)gr*N + gc)     = ll0;
            *reinterpret_cast<__half2*>(outL + (size_t)gr*N + gc + 2) = ll1;
        }
    }
}

// ---------------- final tiny GEMM: (4096,128)x(128,3) ----------------
__global__ void k_cls3(const float* __restrict__ w3, const float* __restrict__ b3,
                       float* __restrict__ out){
    int i = blockIdx.x * blockDim.x + threadIdx.x;
    if (i >= NB * 3) return;
    int b = i / 3, c = i % 3;
    const float* f = g_c2 + (size_t)b * 128;
    float acc = b3[c];
    #pragma unroll 4
    for (int k = 0; k < 128; k++) acc += f[k] * w3[k*3 + c];
    out[i] = acc;
}

// ---------------- launch ----------------
extern "C" void kernel_launch(void* const* d_in, const int* in_sizes, int n_in,
                              void* d_out, int out_size) {
    const float* x      = (const float*)d_in[0];
    const float* in_w   = (const float*)d_in[1];
    const float* in_b   = (const float*)d_in[2];
    const float* pe_w   = (const float*)d_in[3];
    const float* pe_b   = (const float*)d_in[4];
    const float* ln1_w  = (const float*)d_in[5];
    const float* ln1_b  = (const float*)d_in[6];
    const float* qkv_w  = (const float*)d_in[7];
    const float* qkv_b  = (const float*)d_in[8];
    const float* out_w  = (const float*)d_in[9];
    const float* out_b  = (const float*)d_in[10];
    const float* ln2_w  = (const float*)d_in[11];
    const float* ln2_b  = (const float*)d_in[12];
    const float* mlp_w1 = (const float*)d_in[13];
    const float* mlp_b1 = (const float*)d_in[14];
    const float* mlp_w2 = (const float*)d_in[15];
    const float* mlp_b2 = (const float*)d_in[16];
    const float* cls_w1 = (const float*)d_in[17];
    const float* cls_b1 = (const float*)d_in[18];
    const float* cls_w2 = (const float*)d_in[19];
    const float* cls_b2 = (const float*)d_in[20];
    const float* cls_w3 = (const float*)d_in[21];
    const float* cls_b3 = (const float*)d_in[22];
    float* out = (float*)d_out;

    cudaFuncSetAttribute(k_gemm<false,false>, cudaFuncAttributeMaxDynamicSharedMemorySize, GSM_BYTES);
    cudaFuncSetAttribute(k_gemm<false,true>,  cudaFuncAttributeMaxDynamicSharedMemorySize, GSM_BYTES);
    cudaFuncSetAttribute(k_gemm<true,false>,  cudaFuncAttributeMaxDynamicSharedMemorySize, GSM_BYTES);

    float *p_h, *p_qkv, *p_c2f;
    __half *p_fh,*p_fl,*p_nh,*p_nl,*p_oh,*p_ol,*p_gh,*p_gl,*p_hh,*p_hl,*p_c1h,*p_c1l;
    __half *p_peTh,*p_peTl,*p_qkvTh,*p_qkvTl,*p_outTh,*p_outTl;
    __half *p_m1Th,*p_m1Tl,*p_m2Th,*p_m2Tl,*p_c1Th,*p_c1Tl,*p_c2Th,*p_c2Tl;
    cudaGetSymbolAddress((void**)&p_h,    g_h);
    cudaGetSymbolAddress((void**)&p_qkv,  g_qkv);
    cudaGetSymbolAddress((void**)&p_c2f,  g_c2);
    cudaGetSymbolAddress((void**)&p_fh,   g_fh);   cudaGetSymbolAddress((void**)&p_fl,   g_fl);
    cudaGetSymbolAddress((void**)&p_nh,   g_nh);   cudaGetSymbolAddress((void**)&p_nl,   g_nl);
    cudaGetSymbolAddress((void**)&p_oh,   g_oh);   cudaGetSymbolAddress((void**)&p_ol,   g_ol);
    cudaGetSymbolAddress((void**)&p_gh,   g_gh);   cudaGetSymbolAddress((void**)&p_gl,   g_gl);
    cudaGetSymbolAddress((void**)&p_hh,   g_hh);   cudaGetSymbolAddress((void**)&p_hl,   g_hl);
    cudaGetSymbolAddress((void**)&p_c1h,  g_c1h);  cudaGetSymbolAddress((void**)&p_c1l,  g_c1l);
    cudaGetSymbolAddress((void**)&p_peTh, g_peTh); cudaGetSymbolAddress((void**)&p_peTl, g_peTl);
    cudaGetSymbolAddress((void**)&p_qkvTh,g_qkvTh);cudaGetSymbolAddress((void**)&p_qkvTl,g_qkvTl);
    cudaGetSymbolAddress((void**)&p_outTh,g_outTh);cudaGetSymbolAddress((void**)&p_outTl,g_outTl);
    cudaGetSymbolAddress((void**)&p_m1Th, g_m1Th); cudaGetSymbolAddress((void**)&p_m1Tl, g_m1Tl);
    cudaGetSymbolAddress((void**)&p_m2Th, g_m2Th); cudaGetSymbolAddress((void**)&p_m2Tl, g_m2Tl);
    cudaGetSymbolAddress((void**)&p_c1Th, g_c1Th); cudaGetSymbolAddress((void**)&p_c1Tl, g_c1Tl);
    cudaGetSymbolAddress((void**)&p_c2Th, g_c2Th); cudaGetSymbolAddress((void**)&p_c2Tl, g_c2Tl);

    dim3 wb(32, 8);
    k_wsplit<<<dim3(16, 3),  wb>>>(pe_w,  p_peTh, p_peTl, PD, 512);
    for (int i = 0; i < NLAY; i++){
        k_wsplit<<<dim3(48, 16), wb>>>(qkv_w + (size_t)i*HID*1536, p_qkvTh + (size_t)i*1536*HID, p_qkvTl + (size_t)i*1536*HID, HID, 1536);
        k_wsplit<<<dim3(16, 16), wb>>>(out_w + (size_t)i*HID*HID,  p_outTh + (size_t)i*HID*HID,  p_outTl + (size_t)i*HID*HID,  HID, HID);
        k_wsplit<<<dim3(64, 16), wb>>>(mlp_w1 + (size_t)i*HID*MLPH, p_m1Th + (size_t)i*MLPH*HID, p_m1Tl + (size_t)i*MLPH*HID, HID, MLPH);
        k_wsplit<<<dim3(16, 64), wb>>>(mlp_w2 + (size_t)i*MLPH*HID, p_m2Th + (size_t)i*HID*MLPH, p_m2Tl + (size_t)i*HID*MLPH, MLPH, HID);
    }
    k_wsplit<<<dim3(16, 192), wb>>>(cls_w1, p_c1Th, p_c1Tl, 6144, 512);
    k_wsplit<<<dim3(4, 16),   wb>>>(cls_w2, p_c2Th, p_c2Tl, 512, 128);

    k_factors<<<(NB+255)/256, 256>>>(x);
    k_norm<<<(NB*NF+255)/256, 256>>>(in_w, in_b);

    // patch embed -> h (fp32)
    k_gemm<false,false><<<dim3(512/BN, NROWS/BM), 256, GSM_BYTES>>>(
        p_fh, p_fl, p_peTh, p_peTl, pe_b, nullptr, p_h, nullptr, nullptr, NROWS, 512, PD);

    for (int i = 0; i < NLAY; i++){
        k_ln<<<NROWS, 128>>>(p_h, ln1_w + i*HID, ln1_b + i*HID, p_nh, p_nl);
        k_gemm<false,false><<<dim3(1536/BN, NROWS/BM), 256, GSM_BYTES>>>(
            p_nh, p_nl, p_qkvTh + (size_t)i*1536*HID, p_qkvTl + (size_t)i*1536*HID,
            qkv_b + i*1536, nullptr, p_qkv, nullptr, nullptr, NROWS, 1536, HID);
        k_attn<<<NB*8, 64>>>();
        k_gemm<false,true><<<dim3(512/BN, NROWS/BM), 256, GSM_BYTES>>>(
            p_oh, p_ol, p_outTh + (size_t)i*HID*HID, p_outTl + (size_t)i*HID*HID,
            out_b + i*HID, p_h, p_h, nullptr, nullptr, NROWS, HID, HID);
        k_ln<<<NROWS, 128>>>(p_h, ln2_w + i*HID, ln2_b + i*HID, p_nh, p_nl);
        k_gemm<true,false><<<dim3(MLPH/BN, NROWS/BM), 256, GSM_BYTES>>>(
            p_nh, p_nl, p_m1Th + (size_t)i*MLPH*HID, p_m1Tl + (size_t)i*MLPH*HID,
            mlp_b1 + i*MLPH, nullptr, nullptr, p_gh, p_gl, NROWS, MLPH, HID);
        // last layer also emits the hi/lo pair for the cls head (k_split fused away)
        k_gemm<false,true><<<dim3(512/BN, NROWS/BM), 256, GSM_BYTES>>>(
            p_gh, p_gl, p_m2Th + (size_t)i*HID*MLPH, p_m2Tl + (size_t)i*HID*MLPH,
            mlp_b2 + i*HID, p_h, p_h,
            (i == NLAY-1) ? p_hh : nullptr, (i == NLAY-1) ? p_hl : nullptr,
            NROWS, HID, MLPH);
    }

    // cls head: h viewed as (4096, 6144)
    k_gemm<true,false><<<dim3(512/BN, NB/BM), 256, GSM_BYTES>>>(
        p_hh, p_hl, p_c1Th, p_c1Tl, cls_b1, nullptr, nullptr, p_c1h, p_c1l, NB, 512, 6144);
    k_gemm<true,false><<<dim3(1, NB/BM), 256, GSM_BYTES>>>(
        p_c1h, p_c1l, p_c2Th, p_c2Tl, cls_b2, nullptr, p_c2f, nullptr, nullptr, NB, 128, 512);
    k_cls3<<<(NB*3+255)/256, 256>>>(cls_w3, cls_b3, out);
}